// round 10
// baseline (speedup 1.0000x reference)
#include <cuda_runtime.h>

// PatchExtractor: crop(center square of bbox) + bilinear 224x224 + CLIP norm.
// R8: R6 + __launch_bounds__(224,4) so the 48-gather batch actually stays
// resident in registers (true MLP~48), trading occupancy for latency hiding.
//
// img    : [3, 2048, 2048] fp32
// bboxes : [N, 4] int32 (xyxy)
// out    : [N, 3, 224, 224] fp32

#define SIZE 224
#define ROWS_PER_THREAD 4
#define IMG_W 2048
#define IMG_H 2048
#define PLANE (IMG_H * IMG_W)
#define OUT_PLANE (SIZE * SIZE)
#define MAX_N 1024

#define MEAN_R 0.48145466f
#define MEAN_G 0.4578275f
#define MEAN_B 0.40821073f
#define STD_R  0.26862954f
#define STD_G  0.26130258f
#define STD_B  0.27577711f

// Per-patch geometry: {ax, ay, step, unused};  sx = ax + x*step
__device__ float4 g_geom[MAX_N];

__global__ void geom_kernel(const int* __restrict__ bboxes, int N)
{
    int n = blockIdx.x * blockDim.x + threadIdx.x;
    if (n >= N) return;
    const float x0 = (float)bboxes[4 * n + 0];
    const float y0 = (float)bboxes[4 * n + 1];
    const float x1 = (float)bboxes[4 * n + 2];
    const float y1 = (float)bboxes[4 * n + 3];
    const float side = fminf(x1 - x0, y1 - y0);
    const float step = side * (1.0f / (float)SIZE);
    const float ax = 0.5f * (x0 + x1) - 0.5f * side + 0.5f * step - 0.5f;
    const float ay = 0.5f * (y0 + y1) - 0.5f * side + 0.5f * step - 0.5f;
    g_geom[n] = make_float4(ax, ay, step, 0.0f);
}

__global__ __launch_bounds__(SIZE, 4)   // allow ~72 regs: keep all 48 loads live
void patch_extract_kernel(const float* __restrict__ img,
                          float* __restrict__ out)
{
    const int y0 = blockIdx.x * ROWS_PER_THREAD;  // first output row
    const int n  = blockIdx.y;                    // patch
    const int x  = threadIdx.x;                   // output col

    const float4 g = g_geom[n];

    // ---- shared x-geometry (all 4 rows) ----
    float sx = fmaf((float)x, g.z, g.x);
    sx = fminf(fmaxf(sx, 0.0f), (float)(IMG_W - 1));
    const int   ix0 = (int)sx;
    const float fx  = sx - (float)ix0;
    const float ex  = 1.0f - fx;

    // ---- per-row y-geometry ----
    int   o0[ROWS_PER_THREAD];
    float fy[ROWS_PER_THREAD];
    #pragma unroll
    for (int k = 0; k < ROWS_PER_THREAD; ++k) {
        float sy = fmaf((float)(y0 + k), g.z, g.y);
        sy = fminf(fmaxf(sy, 0.0f), (float)(IMG_H - 1));
        const int iy = (int)sy;
        fy[k] = sy - (float)iy;
        o0[k] = (iy << 11) + ix0;     // row iy; iy+1 <= 2047 guaranteed
    }

    const float* __restrict__ p0 = img;
    const float* __restrict__ p1 = img + PLANE;
    const float* __restrict__ p2 = img + 2 * PLANE;

    // ---- hoist all 48 gathers; with 72-reg budget they stay in flight ----
    float pr[ROWS_PER_THREAD][4], pg[ROWS_PER_THREAD][4], pb[ROWS_PER_THREAD][4];
    #pragma unroll
    for (int k = 0; k < ROWS_PER_THREAD; ++k) {
        const int a = o0[k];
        const int b = a + IMG_W;
        pr[k][0] = __ldg(p0 + a); pr[k][1] = __ldg(p0 + a + 1);
        pr[k][2] = __ldg(p0 + b); pr[k][3] = __ldg(p0 + b + 1);
        pg[k][0] = __ldg(p1 + a); pg[k][1] = __ldg(p1 + a + 1);
        pg[k][2] = __ldg(p1 + b); pg[k][3] = __ldg(p1 + b + 1);
        pb[k][0] = __ldg(p2 + a); pb[k][1] = __ldg(p2 + a + 1);
        pb[k][2] = __ldg(p2 + b); pb[k][3] = __ldg(p2 + b + 1);
    }

    const float sR = 1.0f / (255.0f * STD_R), cR = MEAN_R / STD_R;
    const float sG = 1.0f / (255.0f * STD_G), cG = MEAN_G / STD_G;
    const float sB = 1.0f / (255.0f * STD_B), cB = MEAN_B / STD_B;

    // 32-bit output addressing (out_size = 38.5M < 2^31)
    float* __restrict__ dst = out + (n * 3 * OUT_PLANE + y0 * SIZE + x);

    #pragma unroll
    for (int k = 0; k < ROWS_PER_THREAD; ++k) {
        const float eyk = 1.0f - fy[k];
        const float w00 = ex * eyk, w01 = fx * eyk;
        const float w10 = ex * fy[k], w11 = fx * fy[k];

        float vR = pr[k][0] * w00; vR = fmaf(pr[k][1], w01, vR);
        vR = fmaf(pr[k][2], w10, vR); vR = fmaf(pr[k][3], w11, vR);
        float vG = pg[k][0] * w00; vG = fmaf(pg[k][1], w01, vG);
        vG = fmaf(pg[k][2], w10, vG); vG = fmaf(pg[k][3], w11, vG);
        float vB = pb[k][0] * w00; vB = fmaf(pb[k][1], w01, vB);
        vB = fmaf(pb[k][2], w10, vB); vB = fmaf(pb[k][3], w11, vB);

        dst[k * SIZE]                 = fmaf(vR, sR, -cR);
        dst[k * SIZE + OUT_PLANE]     = fmaf(vG, sG, -cG);
        dst[k * SIZE + 2 * OUT_PLANE] = fmaf(vB, sB, -cB);
    }
}

extern "C" void kernel_launch(void* const* d_in, const int* in_sizes, int n_in,
                              void* d_out, int out_size)
{
    const float* img    = (const float*)d_in[0];
    const int*   bboxes = (const int*)d_in[3];
    float* out = (float*)d_out;

    const int N = in_sizes[3] / 4;

    geom_kernel<<<(N + 255) / 256, 256>>>(bboxes, N);

    dim3 grid(SIZE / ROWS_PER_THREAD, N, 1);
    dim3 block(SIZE, 1, 1);
    patch_extract_kernel<<<grid, block>>>(img, out);
}

// round 13
// speedup vs baseline: 1.4074x; 1.4074x over previous
#include <cuda_runtime.h>

// PatchExtractor: crop(center square of bbox) + bilinear 224x224 + CLIP norm.
// R10: R6 base (proven best) + 7 rows/thread, reg cap 36 (occ ~87%),
// dead-clamp removal, streaming stores.
//
// img    : [3, 2048, 2048] fp32
// bboxes : [N, 4] int32 (xyxy)
// out    : [N, 3, 224, 224] fp32

#define SIZE 224
#define ROWS_PER_THREAD 7
#define ROW_TILES (SIZE / ROWS_PER_THREAD)   // 32
#define IMG_W 2048
#define IMG_H 2048
#define PLANE (IMG_H * IMG_W)
#define OUT_PLANE (SIZE * SIZE)
#define MAX_N 1024

#define MEAN_R 0.48145466f
#define MEAN_G 0.4578275f
#define MEAN_B 0.40821073f
#define STD_R  0.26862954f
#define STD_G  0.26130258f
#define STD_B  0.27577711f

// Per-patch geometry: {ax, ay, step, unused};  sx = ax + x*step
__device__ float4 g_geom[MAX_N];

__global__ void geom_kernel(const int* __restrict__ bboxes, int N)
{
    int n = blockIdx.x * blockDim.x + threadIdx.x;
    if (n >= N) return;
    const float x0 = (float)bboxes[4 * n + 0];
    const float y0 = (float)bboxes[4 * n + 1];
    const float x1 = (float)bboxes[4 * n + 2];
    const float y1 = (float)bboxes[4 * n + 3];
    const float side = fminf(x1 - x0, y1 - y0);
    const float step = side * (1.0f / (float)SIZE);
    const float ax = 0.5f * (x0 + x1) - 0.5f * side + 0.5f * step - 0.5f;
    const float ay = 0.5f * (y0 + y1) - 0.5f * side + 0.5f * step - 0.5f;
    g_geom[n] = make_float4(ax, ay, step, 0.0f);
}

__global__ __launch_bounds__(SIZE, 8)   // cap 36 regs: keep occupancy ~87%
void patch_extract_kernel(const float* __restrict__ img,
                          float* __restrict__ out)
{
    const int y0 = blockIdx.x * ROWS_PER_THREAD;  // first output row
    const int n  = blockIdx.y;                    // patch
    const int x  = threadIdx.x;                   // output col

    const float4 g = g_geom[n];

    // ---- shared x-geometry (all rows). Upper clamp provably dead:
    // sx <= x1 - step/2 - 0.5 <= 2046.5. Lower clamp can trigger (sx >= -0.5).
    float sx = fmaf((float)x, g.z, g.x);
    sx = fmaxf(sx, 0.0f);
    const int   ix0 = (int)sx;
    const float fx  = sx - (float)ix0;
    const float ex  = 1.0f - fx;

    const float* __restrict__ p0 = img;
    const float* __restrict__ p1 = img + PLANE;
    const float* __restrict__ p2 = img + 2 * PLANE;

    const float sR = 1.0f / (255.0f * STD_R), cR = MEAN_R / STD_R;
    const float sG = 1.0f / (255.0f * STD_G), cG = MEAN_G / STD_G;
    const float sB = 1.0f / (255.0f * STD_B), cB = MEAN_B / STD_B;

    float* __restrict__ dst = out + (n * 3 * OUT_PLANE + y0 * SIZE + x);

    float syk = fmaf((float)y0, g.z, g.y);

    #pragma unroll
    for (int k = 0; k < ROWS_PER_THREAD; ++k) {
        // y-geometry for this row. Upper clamp dead (sy <= 2046); lower live.
        const float sy = fmaxf(syk, 0.0f);
        const int   iy = (int)sy;
        const float fy = sy - (float)iy;
        syk += g.z;

        const int a = (iy << 11) + ix0;   // row iy;   iy+1 <= 2046 guaranteed
        const int b = a + IMG_W;          // row iy+1

        // 12-load batch (the proven-good MLP granule at high occupancy)
        const float r00 = __ldg(p0 + a), r01 = __ldg(p0 + a + 1);
        const float r10 = __ldg(p0 + b), r11 = __ldg(p0 + b + 1);
        const float g00 = __ldg(p1 + a), g01 = __ldg(p1 + a + 1);
        const float g10 = __ldg(p1 + b), g11 = __ldg(p1 + b + 1);
        const float b00 = __ldg(p2 + a), b01 = __ldg(p2 + a + 1);
        const float b10 = __ldg(p2 + b), b11 = __ldg(p2 + b + 1);

        const float ey  = 1.0f - fy;
        const float w00 = ex * ey, w01 = fx * ey;
        const float w10 = ex * fy, w11 = fx * fy;

        float vR = r00 * w00; vR = fmaf(r01, w01, vR);
        vR = fmaf(r10, w10, vR); vR = fmaf(r11, w11, vR);
        float vG = g00 * w00; vG = fmaf(g01, w01, vG);
        vG = fmaf(g10, w10, vG); vG = fmaf(g11, w11, vG);
        float vB = b00 * w00; vB = fmaf(b01, w01, vB);
        vB = fmaf(b10, w10, vB); vB = fmaf(b11, w11, vB);

        // Streaming stores: output is never re-read; don't pollute L2.
        __stwt(dst + k * SIZE,                 fmaf(vR, sR, -cR));
        __stwt(dst + k * SIZE + OUT_PLANE,     fmaf(vG, sG, -cG));
        __stwt(dst + k * SIZE + 2 * OUT_PLANE, fmaf(vB, sB, -cB));
    }
}

extern "C" void kernel_launch(void* const* d_in, const int* in_sizes, int n_in,
                              void* d_out, int out_size)
{
    const float* img    = (const float*)d_in[0];
    const int*   bboxes = (const int*)d_in[3];
    float* out = (float*)d_out;

    const int N = in_sizes[3] / 4;

    geom_kernel<<<(N + 255) / 256, 256>>>(bboxes, N);

    dim3 grid(ROW_TILES, N, 1);
    dim3 block(SIZE, 1, 1);
    patch_extract_kernel<<<grid, block>>>(img, out);
}